// round 6
// baseline (speedup 1.0000x reference)
#include <cuda_runtime.h>
#include <cstdint>

// out[n,c,oh,ow] = x[n,c,2*oh,2*ow]
//   x:   (8,128,512,512) fp32, contiguous NCHW  -> 268,435,456 elems
//   out: (8,128,256,256) fp32                    ->  67,108,864 elems
//
// Permutes in the reference cancel: encoder NCHW->NHWC, slice (stride 1,2,2,1
// on N,H,W,C), decoder NHWC->NCHW == stride-2 downsample of H and W in NCHW.
//
// Each thread produces TWO output float4 (8 output columns = 16 input
// columns = four input float4 loads, all issued back-to-back for MLP=4).
// Flattened output row r in [0, 8*128*256) maps to input row 2*r.
// Input row = 128 float4; output row = 64 float4 = 32 float8-units.

static constexpr int OUT_F4     = 8 * 128 * 256 * 256 / 4;  // 16,777,216
static constexpr int OUT_UNITS  = OUT_F4 / 2;               //  8,388,608
static constexpr int OW8        = 32;    // 2-float4 units per output row
static constexpr int IN_ROW_F4  = 128;   // float4 per input row

__global__ __launch_bounds__(256) void strided_slice_kernel(
    const float4* __restrict__ in, float4* __restrict__ out)
{
    int i = blockIdx.x * blockDim.x + threadIdx.x;
    if (i >= OUT_UNITS) return;

    int u = i & (OW8 - 1);         // unit index within output row (0..31)
    int r = i >> 5;                // output flattened row
    // input: row 2*r, starting at float col 16*u = float4 col 4*u
    long in_idx  = (long)(2 * r) * IN_ROW_F4 + 4 * u;
    long out_idx = (long)i * 2;

    // 4 independent 128-bit loads, front-batched
    float4 a = __ldcs(in + in_idx);
    float4 b = __ldcs(in + in_idx + 1);
    float4 c = __ldcs(in + in_idx + 2);
    float4 d = __ldcs(in + in_idx + 3);

    float4 o0, o1;
    o0.x = a.x; o0.y = a.z; o0.z = b.x; o0.w = b.z;
    o1.x = c.x; o1.y = c.z; o1.z = d.x; o1.w = d.z;

    __stcs(out + out_idx,     o0);
    __stcs(out + out_idx + 1, o1);
}

extern "C" void kernel_launch(void* const* d_in, const int* in_sizes, int n_in,
                              void* d_out, int out_size)
{
    const float4* in  = (const float4*)d_in[0];
    float4*       out = (float4*)d_out;

    int threads = 256;
    int blocks  = (OUT_UNITS + threads - 1) / threads;  // 32,768
    strided_slice_kernel<<<blocks, threads>>>(in, out);
}

// round 8
// speedup vs baseline: 1.1422x; 1.1422x over previous
#include <cuda_runtime.h>
#include <cstdint>

// out[n,c,oh,ow] = x[n,c,2*oh,2*ow]
//   x:   (8,128,512,512) fp32, contiguous NCHW  -> 268,435,456 elems
//   out: (8,128,256,256) fp32                    ->  67,108,864 elems
//
// One WARP per output row. Input row 2r = 128 float4; output row r = 128
// float2. Lane k loads the contiguous float4 irow[k + 32*j] (j=0..3) —
// fully coalesced, 4 L1 wavefronts per LDG (vs 16 in the strided version).
// The even elements (.x, .z) of lane k's float4 are exactly output floats
// 2k, 2k+1 = output float2 index k: deinterleave is free, no shuffles.
// 4 independent loads front-batched per lane (MLP=4), then 4 coalesced
// STG.64 stores.

static constexpr int OUT_ROWS   = 8 * 128 * 256;  // 262,144 output rows
static constexpr int IN_ROW_F4  = 128;            // float4 per input row
static constexpr int OUT_ROW_F2 = 128;            // float2 per output row
static constexpr int WARPS_PER_BLOCK = 8;         // 256 threads

__global__ __launch_bounds__(256) void strided_slice_kernel(
    const float4* __restrict__ in, float2* __restrict__ out)
{
    int gwarp = (blockIdx.x * blockDim.x + threadIdx.x) >> 5;  // output row r
    int lane  = threadIdx.x & 31;

    // input row 2*r starts at float4 index (2*r)*128 = r*256
    const float4* irow = in  + (long)gwarp * (2 * IN_ROW_F4);
    float2*       orow = out + (long)gwarp * OUT_ROW_F2;

    // 4 independent, warp-contiguous 128-bit loads (512B per warp per LDG)
    float4 a = __ldcs(irow + lane);
    float4 b = __ldcs(irow + lane + 32);
    float4 c = __ldcs(irow + lane + 64);
    float4 d = __ldcs(irow + lane + 96);

    // even elements -> output float2 at the same lane index: free deinterleave
    __stcs(orow + lane,      make_float2(a.x, a.z));
    __stcs(orow + lane + 32, make_float2(b.x, b.z));
    __stcs(orow + lane + 64, make_float2(c.x, c.z));
    __stcs(orow + lane + 96, make_float2(d.x, d.z));
}

extern "C" void kernel_launch(void* const* d_in, const int* in_sizes, int n_in,
                              void* d_out, int out_size)
{
    const float4* in  = (const float4*)d_in[0];
    float2*       out = (float2*)d_out;

    int blocks = OUT_ROWS / WARPS_PER_BLOCK;  // 32,768 blocks x 256 threads
    strided_slice_kernel<<<blocks, 256>>>(in, out);
}